// round 3
// baseline (speedup 1.0000x reference)
#include <cuda_runtime.h>
#include <math.h>
#include <stdint.h>

// Problem constants
#define NB   2
#define NS   2048
#define ND   1024
#define NH   16
#define NHD  64
#define NBH  (NB*NH)       // 32
#define NM   (NB*NS)       // 4096
#define OUT_ELEMS  (NB*NS*ND)                        // 4,194,304
#define ATTN_ELEMS ((long long)NBH*(long long)NS*NS) // 134,217,728

#define NEG_INF __int_as_float(0xff800000)

// ---- scratch (device globals; no runtime allocation allowed) ----
__device__ float g_q[NBH * NS * NHD];
__device__ float g_k[NBH * NS * NHD];
__device__ float g_v[NBH * NS * NHD];
__device__ float g_ctx[NBH * NS * NHD];
__device__ float g_attn_scratch[134217728]; // fallback if out buffer excludes attn
__device__ int   g_mask_is_u8;

// ---------------------------------------------------------------------------
__global__ void detect_mask_kernel(const unsigned char* __restrict__ m) {
    g_mask_is_u8 = (m[1] != 0) ? 1 : 0;
}

// ---------------------------------------------------------------------------
// tf32 helpers: 3xTF32 error-compensated path
// ---------------------------------------------------------------------------
__device__ __forceinline__ unsigned tf32_of(float x) {
    unsigned r;
    asm("cvt.rna.tf32.f32 %0, %1;" : "=r"(r) : "f"(x));
    return r;
}
__device__ __forceinline__ void split_tf32(float x, unsigned* hi, unsigned* lo) {
    unsigned h = tf32_of(x);
    *hi = h;
    *lo = tf32_of(x - __uint_as_float(h));
}
__device__ __forceinline__ void mma8(float* c, const unsigned* a, const unsigned* b) {
    asm volatile(
        "mma.sync.aligned.m16n8k8.row.col.f32.tf32.tf32.f32 "
        "{%0,%1,%2,%3}, {%4,%5,%6,%7}, {%8,%9}, {%0,%1,%2,%3};"
        : "+f"(c[0]), "+f"(c[1]), "+f"(c[2]), "+f"(c[3])
        : "r"(a[0]), "r"(a[1]), "r"(a[2]), "r"(a[3]), "r"(b[0]), "r"(b[1]));
}

// ---------------------------------------------------------------------------
// Projection GEMM: C[M,N] = A[M,1024] @ W[1024,N] + bias, 128x128 block tile.
// 256 threads = 8 warps (2 m x 4 n), warp tile 64x32, mma m16n8k8 tf32 x3.
// ---------------------------------------------------------------------------
__global__ void __launch_bounds__(256)
proj_mma_kernel(const float* __restrict__ A, const float* __restrict__ W,
                const float* __restrict__ bias, float* __restrict__ C,
                int gatherA, int scatterC)
{
    __shared__ unsigned Ah[16][136], Al[16][136], Bh[16][136], Bl[16][136];

    const int tid  = threadIdx.x;
    const int warp = tid >> 5, lane = tid & 31;
    const int gid  = lane >> 2, tig = lane & 3;
    const int wm   = (warp & 1) * 64;
    const int wn   = (warp >> 1) * 32;
    const int row0 = blockIdx.y * 128, col0 = blockIdx.x * 128;

    float acc[4][4][4] = {};

    for (int k0 = 0; k0 < ND; k0 += 16) {
        #pragma unroll
        for (int i = 0; i < 2; i++) {
            int idx = i * 256 + tid;
            int r = idx >> 2, c4 = idx & 3;
            int gr = row0 + r, gk = k0 + c4 * 4;
            float4 a;
            if (gatherA) {
                int b = gr >> 11, s = gr & (NS - 1), h = gk >> 6, d = gk & 63;
                a = *(const float4*)&A[(((size_t)(b * NH + h)) * NS + s) * NHD + d];
            } else {
                a = *(const float4*)&A[(size_t)gr * ND + gk];
            }
            float v[4] = {a.x, a.y, a.z, a.w};
            #pragma unroll
            for (int j = 0; j < 4; j++)
                split_tf32(v[j], &Ah[c4 * 4 + j][r], &Al[c4 * 4 + j][r]);
        }
        #pragma unroll
        for (int i = 0; i < 2; i++) {
            int idx = i * 256 + tid;
            int r = idx >> 5, c4 = idx & 31;
            float4 b = *(const float4*)&W[(size_t)(k0 + r) * ND + col0 + c4 * 4];
            float v[4] = {b.x, b.y, b.z, b.w};
            #pragma unroll
            for (int j = 0; j < 4; j++)
                split_tf32(v[j], &Bh[r][c4 * 4 + j], &Bl[r][c4 * 4 + j]);
        }
        __syncthreads();

        #pragma unroll
        for (int ks = 0; ks < 16; ks += 8) {
            unsigned ah[4][4], al[4][4], bh[4][2], bl[4][2];
            #pragma unroll
            for (int mt = 0; mt < 4; mt++) {
                int m = wm + mt * 16 + gid;
                ah[mt][0] = Ah[ks + tig][m];     ah[mt][1] = Ah[ks + tig][m + 8];
                ah[mt][2] = Ah[ks + tig + 4][m]; ah[mt][3] = Ah[ks + tig + 4][m + 8];
                al[mt][0] = Al[ks + tig][m];     al[mt][1] = Al[ks + tig][m + 8];
                al[mt][2] = Al[ks + tig + 4][m]; al[mt][3] = Al[ks + tig + 4][m + 8];
            }
            #pragma unroll
            for (int nt = 0; nt < 4; nt++) {
                int n = wn + nt * 8 + gid;
                bh[nt][0] = Bh[ks + tig][n]; bh[nt][1] = Bh[ks + tig + 4][n];
                bl[nt][0] = Bl[ks + tig][n]; bl[nt][1] = Bl[ks + tig + 4][n];
            }
            #pragma unroll
            for (int mt = 0; mt < 4; mt++)
                #pragma unroll
                for (int nt = 0; nt < 4; nt++)
                    mma8(acc[mt][nt], ah[mt], bh[nt]);
            #pragma unroll
            for (int mt = 0; mt < 4; mt++)
                #pragma unroll
                for (int nt = 0; nt < 4; nt++)
                    mma8(acc[mt][nt], al[mt], bh[nt]);
            #pragma unroll
            for (int mt = 0; mt < 4; mt++)
                #pragma unroll
                for (int nt = 0; nt < 4; nt++)
                    mma8(acc[mt][nt], ah[mt], bl[nt]);
        }
        __syncthreads();
    }

    #pragma unroll
    for (int mt = 0; mt < 4; mt++) {
        #pragma unroll
        for (int nt = 0; nt < 4; nt++) {
            int n = col0 + wn + nt * 8 + tig * 2;
            float b0 = bias[n], b1 = bias[n + 1];
            #pragma unroll
            for (int h2 = 0; h2 < 2; h2++) {
                int m = row0 + wm + mt * 16 + gid + h2 * 8;
                float c0 = acc[mt][nt][h2 * 2]     + b0;
                float c1 = acc[mt][nt][h2 * 2 + 1] + b1;
                if (scatterC) {
                    int b = m >> 11, s = m & (NS - 1), hh = n >> 6, d = n & 63;
                    *(float2*)&C[(((size_t)(b * NH + hh)) * NS + s) * NHD + d] =
                        make_float2(c0, c1);
                } else {
                    *(float2*)&C[(size_t)m * ND + n] = make_float2(c0, c1);
                }
            }
        }
    }
}

// ---------------------------------------------------------------------------
// Scores: attn[bh,q,k] = mask ? (Q.K)*scale : -inf ; 128x128 tile, HD=64.
// Same warp layout as proj. grid = (kt=16, qt=16, bh=32)
// ---------------------------------------------------------------------------
__global__ void __launch_bounds__(256)
score_mma_kernel(const float* __restrict__ qg, const float* __restrict__ kg,
                 const unsigned char* __restrict__ mask8, float* __restrict__ attn)
{
    __shared__ unsigned Qh[16][136], Ql[16][136], Kh[16][136], Kl[16][136];

    const int tid  = threadIdx.x;
    const int warp = tid >> 5, lane = tid & 31;
    const int gid  = lane >> 2, tig = lane & 3;
    const int wm   = (warp & 1) * 64;
    const int wn   = (warp >> 1) * 32;
    const int kt = blockIdx.x, qt = blockIdx.y, bh_i = blockIdx.z;

    const float* q = qg + (size_t)bh_i * NS * NHD;
    const float* k = kg + (size_t)bh_i * NS * NHD;

    float acc[4][4][4] = {};

    for (int d0 = 0; d0 < NHD; d0 += 16) {
        #pragma unroll
        for (int i = 0; i < 2; i++) {
            int idx = i * 256 + tid;
            int r = idx >> 2, c4 = idx & 3;
            float4 a = *(const float4*)&q[(size_t)(qt * 128 + r) * NHD + d0 + c4 * 4];
            float va[4] = {a.x, a.y, a.z, a.w};
            #pragma unroll
            for (int j = 0; j < 4; j++)
                split_tf32(va[j], &Qh[c4 * 4 + j][r], &Ql[c4 * 4 + j][r]);
            float4 b = *(const float4*)&k[(size_t)(kt * 128 + r) * NHD + d0 + c4 * 4];
            float vb[4] = {b.x, b.y, b.z, b.w};
            #pragma unroll
            for (int j = 0; j < 4; j++)
                split_tf32(vb[j], &Kh[c4 * 4 + j][r], &Kl[c4 * 4 + j][r]);
        }
        __syncthreads();

        #pragma unroll
        for (int ks = 0; ks < 16; ks += 8) {
            unsigned ah[4][4], al[4][4], bh[4][2], bl[4][2];
            #pragma unroll
            for (int mt = 0; mt < 4; mt++) {
                int m = wm + mt * 16 + gid;
                ah[mt][0] = Qh[ks + tig][m];     ah[mt][1] = Qh[ks + tig][m + 8];
                ah[mt][2] = Qh[ks + tig + 4][m]; ah[mt][3] = Qh[ks + tig + 4][m + 8];
                al[mt][0] = Ql[ks + tig][m];     al[mt][1] = Ql[ks + tig][m + 8];
                al[mt][2] = Ql[ks + tig + 4][m]; al[mt][3] = Ql[ks + tig + 4][m + 8];
            }
            #pragma unroll
            for (int nt = 0; nt < 4; nt++) {
                int n = wn + nt * 8 + gid;
                bh[nt][0] = Kh[ks + tig][n]; bh[nt][1] = Kh[ks + tig + 4][n];
                bl[nt][0] = Kl[ks + tig][n]; bl[nt][1] = Kl[ks + tig + 4][n];
            }
            #pragma unroll
            for (int mt = 0; mt < 4; mt++)
                #pragma unroll
                for (int nt = 0; nt < 4; nt++)
                    mma8(acc[mt][nt], ah[mt], bh[nt]);
            #pragma unroll
            for (int mt = 0; mt < 4; mt++)
                #pragma unroll
                for (int nt = 0; nt < 4; nt++)
                    mma8(acc[mt][nt], al[mt], bh[nt]);
            #pragma unroll
            for (int mt = 0; mt < 4; mt++)
                #pragma unroll
                for (int nt = 0; nt < 4; nt++)
                    mma8(acc[mt][nt], ah[mt], bl[nt]);
        }
        __syncthreads();
    }

    const float scale = 0.125f;
    const int use8 = g_mask_is_u8;
    const int* mask32 = (const int*)mask8;

    #pragma unroll
    for (int mt = 0; mt < 4; mt++) {
        #pragma unroll
        for (int nt = 0; nt < 4; nt++) {
            int n = kt * 128 + wn + nt * 8 + tig * 2;
            #pragma unroll
            for (int h2 = 0; h2 < 2; h2++) {
                int m = qt * 128 + wm + mt * 16 + gid + h2 * 8;
                float c0 = acc[mt][nt][h2 * 2]     * scale;
                float c1 = acc[mt][nt][h2 * 2 + 1] * scale;
                bool m0, m1;
                if (use8) {
                    uchar2 mv = *(const uchar2*)&mask8[(size_t)m * NS + n];
                    m0 = mv.x != 0; m1 = mv.y != 0;
                } else {
                    int2 mv = *(const int2*)&mask32[(size_t)m * NS + n];
                    m0 = mv.x != 0; m1 = mv.y != 0;
                }
                float2 o = make_float2(m0 ? c0 : NEG_INF, m1 ? c1 : NEG_INF);
                *(float2*)&attn[((size_t)bh_i * NS + m) * NS + n] = o;
            }
        }
    }
}

// ---------------------------------------------------------------------------
// Row softmax over 2048 elements, in place. grid = 65536 rows, block = 256.
// ---------------------------------------------------------------------------
__global__ void softmax_kernel(float* __restrict__ attn)
{
    const size_t row = blockIdx.x;
    float* p = attn + row * (size_t)NS;
    const int tid = threadIdx.x;

    float v[8];
    float mx = NEG_INF;
    #pragma unroll
    for (int i = 0; i < 8; i++) {
        v[i] = p[tid + i * 256];
        mx = fmaxf(mx, v[i]);
    }

    __shared__ float sh[8];
    #pragma unroll
    for (int o = 16; o > 0; o >>= 1)
        mx = fmaxf(mx, __shfl_xor_sync(0xffffffffu, mx, o));
    if ((tid & 31) == 0) sh[tid >> 5] = mx;
    __syncthreads();
    if (tid < 32) {
        float m2 = (tid < 8) ? sh[tid] : NEG_INF;
        #pragma unroll
        for (int o = 4; o > 0; o >>= 1)
            m2 = fmaxf(m2, __shfl_xor_sync(0xffffffffu, m2, o));
        if (tid == 0) sh[0] = m2;
    }
    __syncthreads();
    mx = sh[0];
    __syncthreads();

    float s = 0.0f;
    #pragma unroll
    for (int i = 0; i < 8; i++) {
        v[i] = __expf(v[i] - mx);
        s += v[i];
    }
    #pragma unroll
    for (int o = 16; o > 0; o >>= 1)
        s += __shfl_xor_sync(0xffffffffu, s, o);
    if ((tid & 31) == 0) sh[tid >> 5] = s;
    __syncthreads();
    if (tid < 32) {
        float s2 = (tid < 8) ? sh[tid] : 0.0f;
        #pragma unroll
        for (int o = 4; o > 0; o >>= 1)
            s2 += __shfl_xor_sync(0xffffffffu, s2, o);
        if (tid == 0) sh[0] = s2;
    }
    __syncthreads();
    const float inv = 1.0f / sh[0];

    #pragma unroll
    for (int i = 0; i < 8; i++)
        p[tid + i * 256] = v[i] * inv;
}

// ---------------------------------------------------------------------------
// PV: ctx[bh,q,d] = sum_k attn[bh,q,k] * V[bh,k,d]
// Block tile 128(q) x 64(d), ktile 16. 256 threads = 8 warps (4 m x 2 n),
// warp tile 32x32. grid = (qt=16, bh=32)
// ---------------------------------------------------------------------------
__global__ void __launch_bounds__(256)
av_mma_kernel(const float* __restrict__ attn, const float* __restrict__ vg,
              float* __restrict__ ctx)
{
    __shared__ unsigned Ph[16][136], Pl[16][136], Vh[16][72], Vl[16][72];

    const int tid  = threadIdx.x;
    const int warp = tid >> 5, lane = tid & 31;
    const int gid  = lane >> 2, tig = lane & 3;
    const int wm   = (warp & 3) * 32;
    const int wn   = (warp >> 2) * 32;
    const int qt = blockIdx.x, bh_i = blockIdx.y;

    const float* v    = vg + (size_t)bh_i * NS * NHD;
    const float* prow = attn + ((size_t)bh_i * NS + qt * 128) * NS;

    float acc[2][4][4] = {};

    for (int k0 = 0; k0 < NS; k0 += 16) {
        #pragma unroll
        for (int i = 0; i < 2; i++) {
            int idx = i * 256 + tid;
            int r = idx >> 2, c4 = idx & 3;
            float4 a = *(const float4*)&prow[(size_t)r * NS + k0 + c4 * 4];
            float va[4] = {a.x, a.y, a.z, a.w};
            #pragma unroll
            for (int j = 0; j < 4; j++)
                split_tf32(va[j], &Ph[c4 * 4 + j][r], &Pl[c4 * 4 + j][r]);
        }
        {
            int r = tid >> 4, c4 = tid & 15;
            float4 b = *(const float4*)&v[(size_t)(k0 + r) * NHD + c4 * 4];
            float vb[4] = {b.x, b.y, b.z, b.w};
            #pragma unroll
            for (int j = 0; j < 4; j++)
                split_tf32(vb[j], &Vh[r][c4 * 4 + j], &Vl[r][c4 * 4 + j]);
        }
        __syncthreads();

        #pragma unroll
        for (int ks = 0; ks < 16; ks += 8) {
            unsigned ah[2][4], al[2][4], bh[4][2], bl[4][2];
            #pragma unroll
            for (int mt = 0; mt < 2; mt++) {
                int m = wm + mt * 16 + gid;
                ah[mt][0] = Ph[ks + tig][m];     ah[mt][1] = Ph[ks + tig][m + 8];
                ah[mt][2] = Ph[ks + tig + 4][m]; ah[mt][3] = Ph[ks + tig + 4][m + 8];
                al[mt][0] = Pl[ks + tig][m];     al[mt][1] = Pl[ks + tig][m + 8];
                al[mt][2] = Pl[ks + tig + 4][m]; al[mt][3] = Pl[ks + tig + 4][m + 8];
            }
            #pragma unroll
            for (int nt = 0; nt < 4; nt++) {
                int n = wn + nt * 8 + gid;
                bh[nt][0] = Vh[ks + tig][n]; bh[nt][1] = Vh[ks + tig + 4][n];
                bl[nt][0] = Vl[ks + tig][n]; bl[nt][1] = Vl[ks + tig + 4][n];
            }
            #pragma unroll
            for (int mt = 0; mt < 2; mt++)
                #pragma unroll
                for (int nt = 0; nt < 4; nt++)
                    mma8(acc[mt][nt], ah[mt], bh[nt]);
            #pragma unroll
            for (int mt = 0; mt < 2; mt++)
                #pragma unroll
                for (int nt = 0; nt < 4; nt++)
                    mma8(acc[mt][nt], al[mt], bh[nt]);
            #pragma unroll
            for (int mt = 0; mt < 2; mt++)
                #pragma unroll
                for (int nt = 0; nt < 4; nt++)
                    mma8(acc[mt][nt], ah[mt], bl[nt]);
        }
        __syncthreads();
    }

    #pragma unroll
    for (int mt = 0; mt < 2; mt++) {
        #pragma unroll
        for (int nt = 0; nt < 4; nt++) {
            int n = wn + nt * 8 + tig * 2;
            #pragma unroll
            for (int h2 = 0; h2 < 2; h2++) {
                int m = qt * 128 + wm + mt * 16 + gid + h2 * 8;
                float2 o = make_float2(acc[mt][nt][h2 * 2], acc[mt][nt][h2 * 2 + 1]);
                *(float2*)&ctx[((size_t)bh_i * NS + m) * NHD + n] = o;
            }
        }
    }
}

// ---------------------------------------------------------------------------
extern "C" void kernel_launch(void* const* d_in, const int* in_sizes, int n_in,
                              void* d_out, int out_size)
{
    (void)in_sizes; (void)n_in;

    const float* query = (const float*)d_in[0];
    const float* key   = (const float*)d_in[1];
    const float* value = (const float*)d_in[2];
    const float* Wq    = (const float*)d_in[3];
    const float* bq    = (const float*)d_in[4];
    const float* Wk    = (const float*)d_in[5];
    const float* bk    = (const float*)d_in[6];
    const float* Wv    = (const float*)d_in[7];
    const float* bv    = (const float*)d_in[8];
    const float* Wo    = (const float*)d_in[9];
    const float* bo    = (const float*)d_in[10];
    const unsigned char* mask = (const unsigned char*)d_in[11];

    float* out = (float*)d_out;

    float *qp, *kp, *vp, *ctxp, *attn;
    cudaGetSymbolAddress((void**)&qp,   g_q);
    cudaGetSymbolAddress((void**)&kp,   g_k);
    cudaGetSymbolAddress((void**)&vp,   g_v);
    cudaGetSymbolAddress((void**)&ctxp, g_ctx);

    if ((long long)out_size >= (long long)OUT_ELEMS + ATTN_ELEMS) {
        attn = out + OUT_ELEMS;             // harness output = concat(out, attn)
    } else {
        cudaGetSymbolAddress((void**)&attn, g_attn_scratch);
    }

    detect_mask_kernel<<<1, 1>>>(mask);

    dim3 blk(256);
    dim3 gproj(ND / 128, NM / 128);  // (8, 32)
    proj_mma_kernel<<<gproj, blk>>>(query, Wq, bq, qp, 0, 1);
    proj_mma_kernel<<<gproj, blk>>>(key,   Wk, bk, kp, 0, 1);
    proj_mma_kernel<<<gproj, blk>>>(value, Wv, bv, vp, 0, 1);

    dim3 gscore(NS / 128, NS / 128, NBH);    // (16, 16, 32)
    score_mma_kernel<<<gscore, blk>>>(qp, kp, mask, attn);

    softmax_kernel<<<NBH * NS, blk>>>(attn);

    dim3 gav(NS / 128, NBH);                 // (16, 32)
    av_mma_kernel<<<gav, blk>>>(attn, vp, ctxp);

    proj_mma_kernel<<<gproj, blk>>>(ctxp, Wo, bo, out, 1, 0);
}

// round 4
// speedup vs baseline: 2.0317x; 2.0317x over previous
#include <cuda_runtime.h>
#include <cuda_bf16.h>
#include <math.h>
#include <stdint.h>

// Problem constants
#define NB   2
#define NS   2048
#define ND   1024
#define NH   16
#define NHD  64
#define NBH  (NB*NH)       // 32
#define NM   (NB*NS)       // 4096
#define OUT_ELEMS  (NB*NS*ND)                        // 4,194,304
#define ATTN_ELEMS ((long long)NBH*(long long)NS*NS) // 134,217,728

#define NEG_INF __int_as_float(0xff800000)

// ---- scratch (device globals; no runtime allocation allowed) ----
__device__ float g_q[NBH * NS * NHD];
__device__ float g_k[NBH * NS * NHD];
__device__ float g_v[NBH * NS * NHD];
__device__ float g_ctx[NBH * NS * NHD];
__device__ float g_attn_scratch[134217728]; // fallback if out buffer excludes attn
__device__ int   g_mask_is_u8;

// ---------------------------------------------------------------------------
__global__ void detect_mask_kernel(const unsigned char* __restrict__ m) {
    g_mask_is_u8 = (m[1] != 0) ? 1 : 0;
}

// ---------------------------------------------------------------------------
// 3xBF16 helpers. Pack two consecutive-k values into one u32 (lo 16 = even k).
// x = hi + lo with |lo| <= 2^-8|x|, dropped term lo*lo ~ 2^-16 relative.
// ---------------------------------------------------------------------------
__device__ __forceinline__ void split2(float x0, float x1,
                                       unsigned& hi, unsigned& lo) {
    __nv_bfloat16 h0 = __float2bfloat16(x0);
    __nv_bfloat16 h1 = __float2bfloat16(x1);
    __nv_bfloat162 hp = __halves2bfloat162(h0, h1);
    hi = *reinterpret_cast<unsigned*>(&hp);
    float l0 = x0 - __bfloat162float(h0);
    float l1 = x1 - __bfloat162float(h1);
    __nv_bfloat162 lp = __floats2bfloat162_rn(l0, l1);
    lo = *reinterpret_cast<unsigned*>(&lp);
}

__device__ __forceinline__ void mma16(float* c, const unsigned* a, const unsigned* b) {
    asm volatile(
        "mma.sync.aligned.m16n8k16.row.col.f32.bf16.bf16.f32 "
        "{%0,%1,%2,%3}, {%4,%5,%6,%7}, {%8,%9}, {%0,%1,%2,%3};"
        : "+f"(c[0]), "+f"(c[1]), "+f"(c[2]), "+f"(c[3])
        : "r"(a[0]), "r"(a[1]), "r"(a[2]), "r"(a[3]), "r"(b[0]), "r"(b[1]));
}

// ---------------------------------------------------------------------------
// Projection GEMM: C[4096,1024] = A @ W + bias. 128x128 block, ktile 32.
// 8 warps (2m x 4n), warp tile 64x32, mma m16n8k16 bf16, 3-term compensation.
// smem tiles indexed [kp][*] where kp = k/2 (packed bf16x2 along k).
// ---------------------------------------------------------------------------
__global__ void __launch_bounds__(256, 2)
proj_mma_kernel(const float* __restrict__ A, const float* __restrict__ W,
                const float* __restrict__ bias, float* __restrict__ C,
                int gatherA, int scatterC)
{
    __shared__ unsigned Ah[16][136], Al[16][136], Bh[16][136], Bl[16][136];

    const int tid  = threadIdx.x;
    const int warp = tid >> 5, lane = tid & 31;
    const int gid  = lane >> 2, tig = lane & 3;
    const int wm   = (warp & 1) * 64;
    const int wn   = (warp >> 1) * 32;
    const int row0 = blockIdx.y * 128, col0 = blockIdx.x * 128;

    float acc[4][4][4] = {};

    for (int k0 = 0; k0 < ND; k0 += 32) {
        // A tile: 128 rows x 32 k = 1024 float4, 4/thread; pack k-pairs
        #pragma unroll
        for (int i = 0; i < 4; i++) {
            int idx = i * 256 + tid;
            int r = idx >> 3, c4 = idx & 7;
            int gr = row0 + r, gk = k0 + c4 * 4;
            float4 a;
            if (gatherA) {
                int b = gr >> 11, s = gr & (NS - 1), h = gk >> 6, d = gk & 63;
                a = *(const float4*)&A[(((size_t)(b * NH + h)) * NS + s) * NHD + d];
            } else {
                a = *(const float4*)&A[(size_t)gr * ND + gk];
            }
            split2(a.x, a.y, Ah[c4 * 2][r],     Al[c4 * 2][r]);
            split2(a.z, a.w, Ah[c4 * 2 + 1][r], Al[c4 * 2 + 1][r]);
        }
        // B tile: 32 k x 128 n. Two float4 rows (k, k+1) -> 4 packed u32.
        // tasks: 16 kp x 32 n4 = 512, 2/thread
        #pragma unroll
        for (int i = 0; i < 2; i++) {
            int idx = i * 256 + tid;
            int kp = idx >> 5, n4 = idx & 31;
            const float* b0p = &W[(size_t)(k0 + 2 * kp) * ND + col0 + n4 * 4];
            float4 r0 = *(const float4*)b0p;
            float4 r1 = *(const float4*)(b0p + ND);
            split2(r0.x, r1.x, Bh[kp][n4 * 4 + 0], Bl[kp][n4 * 4 + 0]);
            split2(r0.y, r1.y, Bh[kp][n4 * 4 + 1], Bl[kp][n4 * 4 + 1]);
            split2(r0.z, r1.z, Bh[kp][n4 * 4 + 2], Bl[kp][n4 * 4 + 2]);
            split2(r0.w, r1.w, Bh[kp][n4 * 4 + 3], Bl[kp][n4 * 4 + 3]);
        }
        __syncthreads();

        #pragma unroll
        for (int ks = 0; ks < 2; ks++) {
            const int kpo = ks * 8;
            unsigned ah[4][4], bx[4][2], al[4][4];
            #pragma unroll
            for (int mt = 0; mt < 4; mt++) {
                int m = wm + mt * 16 + gid;
                ah[mt][0] = Ah[kpo + tig][m];     ah[mt][1] = Ah[kpo + tig][m + 8];
                ah[mt][2] = Ah[kpo + 4 + tig][m]; ah[mt][3] = Ah[kpo + 4 + tig][m + 8];
            }
            #pragma unroll
            for (int nt = 0; nt < 4; nt++) {
                int n = wn + nt * 8 + gid;
                bx[nt][0] = Bh[kpo + tig][n]; bx[nt][1] = Bh[kpo + 4 + tig][n];
            }
            #pragma unroll
            for (int mt = 0; mt < 4; mt++)
                #pragma unroll
                for (int nt = 0; nt < 4; nt++)
                    mma16(acc[mt][nt], ah[mt], bx[nt]);   // hi*hi
            #pragma unroll
            for (int mt = 0; mt < 4; mt++) {
                int m = wm + mt * 16 + gid;
                al[mt][0] = Al[kpo + tig][m];     al[mt][1] = Al[kpo + tig][m + 8];
                al[mt][2] = Al[kpo + 4 + tig][m]; al[mt][3] = Al[kpo + 4 + tig][m + 8];
            }
            #pragma unroll
            for (int mt = 0; mt < 4; mt++)
                #pragma unroll
                for (int nt = 0; nt < 4; nt++)
                    mma16(acc[mt][nt], al[mt], bx[nt]);   // lo*hi
            #pragma unroll
            for (int nt = 0; nt < 4; nt++) {
                int n = wn + nt * 8 + gid;
                bx[nt][0] = Bl[kpo + tig][n]; bx[nt][1] = Bl[kpo + 4 + tig][n];
            }
            #pragma unroll
            for (int mt = 0; mt < 4; mt++)
                #pragma unroll
                for (int nt = 0; nt < 4; nt++)
                    mma16(acc[mt][nt], ah[mt], bx[nt]);   // hi*lo
        }
        __syncthreads();
    }

    #pragma unroll
    for (int mt = 0; mt < 4; mt++) {
        #pragma unroll
        for (int nt = 0; nt < 4; nt++) {
            int n = col0 + wn + nt * 8 + tig * 2;
            float b0 = bias[n], b1 = bias[n + 1];
            #pragma unroll
            for (int h2 = 0; h2 < 2; h2++) {
                int m = row0 + wm + mt * 16 + gid + h2 * 8;
                float c0 = acc[mt][nt][h2 * 2]     + b0;
                float c1 = acc[mt][nt][h2 * 2 + 1] + b1;
                if (scatterC) {
                    int b = m >> 11, s = m & (NS - 1), hh = n >> 6, d = n & 63;
                    *(float2*)&C[(((size_t)(b * NH + hh)) * NS + s) * NHD + d] =
                        make_float2(c0, c1);
                } else {
                    *(float2*)&C[(size_t)m * ND + n] = make_float2(c0, c1);
                }
            }
        }
    }
}

// ---------------------------------------------------------------------------
// Scores: attn[bh,q,k] = mask ? (Q.K)*scale : -inf ; 128x128 tile, HD=64.
// grid = (kt=16, qt=16, bh=32)
// ---------------------------------------------------------------------------
__global__ void __launch_bounds__(256, 2)
score_mma_kernel(const float* __restrict__ qg, const float* __restrict__ kg,
                 const unsigned char* __restrict__ mask8, float* __restrict__ attn)
{
    __shared__ unsigned Qh[16][136], Ql[16][136], Kh[16][136], Kl[16][136];

    const int tid  = threadIdx.x;
    const int warp = tid >> 5, lane = tid & 31;
    const int gid  = lane >> 2, tig = lane & 3;
    const int wm   = (warp & 1) * 64;
    const int wn   = (warp >> 1) * 32;
    const int kt = blockIdx.x, qt = blockIdx.y, bh_i = blockIdx.z;

    const float* q = qg + (size_t)bh_i * NS * NHD;
    const float* k = kg + (size_t)bh_i * NS * NHD;

    float acc[4][4][4] = {};

    for (int d0 = 0; d0 < NHD; d0 += 32) {
        // Q/K tiles: 128 rows x 32 d = 1024 float4 each, pack d-pairs
        #pragma unroll
        for (int i = 0; i < 4; i++) {
            int idx = i * 256 + tid;
            int r = idx >> 3, c4 = idx & 7;
            float4 a = *(const float4*)&q[(size_t)(qt * 128 + r) * NHD + d0 + c4 * 4];
            split2(a.x, a.y, Qh[c4 * 2][r],     Ql[c4 * 2][r]);
            split2(a.z, a.w, Qh[c4 * 2 + 1][r], Ql[c4 * 2 + 1][r]);
            float4 b = *(const float4*)&k[(size_t)(kt * 128 + r) * NHD + d0 + c4 * 4];
            split2(b.x, b.y, Kh[c4 * 2][r],     Kl[c4 * 2][r]);
            split2(b.z, b.w, Kh[c4 * 2 + 1][r], Kl[c4 * 2 + 1][r]);
        }
        __syncthreads();

        #pragma unroll
        for (int ks = 0; ks < 2; ks++) {
            const int kpo = ks * 8;
            unsigned ah[4][4], bx[4][2], al[4][4];
            #pragma unroll
            for (int mt = 0; mt < 4; mt++) {
                int m = wm + mt * 16 + gid;
                ah[mt][0] = Qh[kpo + tig][m];     ah[mt][1] = Qh[kpo + tig][m + 8];
                ah[mt][2] = Qh[kpo + 4 + tig][m]; ah[mt][3] = Qh[kpo + 4 + tig][m + 8];
            }
            #pragma unroll
            for (int nt = 0; nt < 4; nt++) {
                int n = wn + nt * 8 + gid;
                bx[nt][0] = Kh[kpo + tig][n]; bx[nt][1] = Kh[kpo + 4 + tig][n];
            }
            #pragma unroll
            for (int mt = 0; mt < 4; mt++)
                #pragma unroll
                for (int nt = 0; nt < 4; nt++)
                    mma16(acc[mt][nt], ah[mt], bx[nt]);
            #pragma unroll
            for (int mt = 0; mt < 4; mt++) {
                int m = wm + mt * 16 + gid;
                al[mt][0] = Ql[kpo + tig][m];     al[mt][1] = Ql[kpo + tig][m + 8];
                al[mt][2] = Ql[kpo + 4 + tig][m]; al[mt][3] = Ql[kpo + 4 + tig][m + 8];
            }
            #pragma unroll
            for (int mt = 0; mt < 4; mt++)
                #pragma unroll
                for (int nt = 0; nt < 4; nt++)
                    mma16(acc[mt][nt], al[mt], bx[nt]);
            #pragma unroll
            for (int nt = 0; nt < 4; nt++) {
                int n = wn + nt * 8 + gid;
                bx[nt][0] = Kl[kpo + tig][n]; bx[nt][1] = Kl[kpo + 4 + tig][n];
            }
            #pragma unroll
            for (int mt = 0; mt < 4; mt++)
                #pragma unroll
                for (int nt = 0; nt < 4; nt++)
                    mma16(acc[mt][nt], ah[mt], bx[nt]);
        }
        __syncthreads();
    }

    const float scale = 0.125f;
    const int use8 = g_mask_is_u8;
    const int* mask32 = (const int*)mask8;

    #pragma unroll
    for (int mt = 0; mt < 4; mt++) {
        #pragma unroll
        for (int nt = 0; nt < 4; nt++) {
            int n = kt * 128 + wn + nt * 8 + tig * 2;
            #pragma unroll
            for (int h2 = 0; h2 < 2; h2++) {
                int m = qt * 128 + wm + mt * 16 + gid + h2 * 8;
                float c0 = acc[mt][nt][h2 * 2]     * scale;
                float c1 = acc[mt][nt][h2 * 2 + 1] * scale;
                bool m0, m1;
                if (use8) {
                    uchar2 mv = *(const uchar2*)&mask8[(size_t)m * NS + n];
                    m0 = mv.x != 0; m1 = mv.y != 0;
                } else {
                    int2 mv = *(const int2*)&mask32[(size_t)m * NS + n];
                    m0 = mv.x != 0; m1 = mv.y != 0;
                }
                float2 o = make_float2(m0 ? c0 : NEG_INF, m1 ? c1 : NEG_INF);
                *(float2*)&attn[((size_t)bh_i * NS + m) * NS + n] = o;
            }
        }
    }
}

// ---------------------------------------------------------------------------
// Row softmax over 2048 elements, in place. grid = 65536 rows, block = 256.
// ---------------------------------------------------------------------------
__global__ void softmax_kernel(float* __restrict__ attn)
{
    const size_t row = blockIdx.x;
    float* p = attn + row * (size_t)NS;
    const int tid = threadIdx.x;

    float v[8];
    float mx = NEG_INF;
    #pragma unroll
    for (int i = 0; i < 8; i++) {
        v[i] = p[tid + i * 256];
        mx = fmaxf(mx, v[i]);
    }

    __shared__ float sh[8];
    #pragma unroll
    for (int o = 16; o > 0; o >>= 1)
        mx = fmaxf(mx, __shfl_xor_sync(0xffffffffu, mx, o));
    if ((tid & 31) == 0) sh[tid >> 5] = mx;
    __syncthreads();
    if (tid < 32) {
        float m2 = (tid < 8) ? sh[tid] : NEG_INF;
        #pragma unroll
        for (int o = 4; o > 0; o >>= 1)
            m2 = fmaxf(m2, __shfl_xor_sync(0xffffffffu, m2, o));
        if (tid == 0) sh[0] = m2;
    }
    __syncthreads();
    mx = sh[0];
    __syncthreads();

    float s = 0.0f;
    #pragma unroll
    for (int i = 0; i < 8; i++) {
        v[i] = __expf(v[i] - mx);
        s += v[i];
    }
    #pragma unroll
    for (int o = 16; o > 0; o >>= 1)
        s += __shfl_xor_sync(0xffffffffu, s, o);
    if ((tid & 31) == 0) sh[tid >> 5] = s;
    __syncthreads();
    if (tid < 32) {
        float s2 = (tid < 8) ? sh[tid] : 0.0f;
        #pragma unroll
        for (int o = 4; o > 0; o >>= 1)
            s2 += __shfl_xor_sync(0xffffffffu, s2, o);
        if (tid == 0) sh[0] = s2;
    }
    __syncthreads();
    const float inv = 1.0f / sh[0];

    #pragma unroll
    for (int i = 0; i < 8; i++)
        p[tid + i * 256] = v[i] * inv;
}

// ---------------------------------------------------------------------------
// PV: ctx[bh,q,d] = sum_k attn[bh,q,k] * V[bh,k,d]
// Block tile 128(q) x 64(d), ktile 32. 8 warps (4m x 2n), warp 32x32.
// grid = (qt=16, bh=32)
// ---------------------------------------------------------------------------
__global__ void __launch_bounds__(256, 2)
av_mma_kernel(const float* __restrict__ attn, const float* __restrict__ vg,
              float* __restrict__ ctx)
{
    __shared__ unsigned Ph[16][136], Pl[16][136], Vh[16][72], Vl[16][72];

    const int tid  = threadIdx.x;
    const int warp = tid >> 5, lane = tid & 31;
    const int gid  = lane >> 2, tig = lane & 3;
    const int wm   = (warp & 3) * 32;
    const int wn   = (warp >> 2) * 32;
    const int qt = blockIdx.x, bh_i = blockIdx.y;

    const float* v    = vg + (size_t)bh_i * NS * NHD;
    const float* prow = attn + ((size_t)bh_i * NS + qt * 128) * NS;

    float acc[2][4][4] = {};

    for (int k0 = 0; k0 < NS; k0 += 32) {
        // P tile: 128 q x 32 k = 1024 float4, 4/thread, pack k-pairs
        #pragma unroll
        for (int i = 0; i < 4; i++) {
            int idx = i * 256 + tid;
            int r = idx >> 3, c4 = idx & 7;
            float4 a = *(const float4*)&prow[(size_t)r * NS + k0 + c4 * 4];
            split2(a.x, a.y, Ph[c4 * 2][r],     Pl[c4 * 2][r]);
            split2(a.z, a.w, Ph[c4 * 2 + 1][r], Pl[c4 * 2 + 1][r]);
        }
        // V tile: 32 k x 64 d; paired rows: 16 kp x 16 d4 = 256 tasks, 1/thread
        {
            int kp = tid >> 4, d4 = tid & 15;
            const float* vp = &v[(size_t)(k0 + 2 * kp) * NHD + d4 * 4];
            float4 r0 = *(const float4*)vp;
            float4 r1 = *(const float4*)(vp + NHD);
            split2(r0.x, r1.x, Vh[kp][d4 * 4 + 0], Vl[kp][d4 * 4 + 0]);
            split2(r0.y, r1.y, Vh[kp][d4 * 4 + 1], Vl[kp][d4 * 4 + 1]);
            split2(r0.z, r1.z, Vh[kp][d4 * 4 + 2], Vl[kp][d4 * 4 + 2]);
            split2(r0.w, r1.w, Vh[kp][d4 * 4 + 3], Vl[kp][d4 * 4 + 3]);
        }
        __syncthreads();

        #pragma unroll
        for (int ks = 0; ks < 2; ks++) {
            const int kpo = ks * 8;
            unsigned ah[2][4], bx[4][2], al[2][4];
            #pragma unroll
            for (int mt = 0; mt < 2; mt++) {
                int m = wm + mt * 16 + gid;
                ah[mt][0] = Ph[kpo + tig][m];     ah[mt][1] = Ph[kpo + tig][m + 8];
                ah[mt][2] = Ph[kpo + 4 + tig][m]; ah[mt][3] = Ph[kpo + 4 + tig][m + 8];
            }
            #pragma unroll
            for (int nt = 0; nt < 4; nt++) {
                int n = wn + nt * 8 + gid;
                bx[nt][0] = Vh[kpo + tig][n]; bx[nt][1] = Vh[kpo + 4 + tig][n];
            }
            #pragma unroll
            for (int mt = 0; mt < 2; mt++)
                #pragma unroll
                for (int nt = 0; nt < 4; nt++)
                    mma16(acc[mt][nt], ah[mt], bx[nt]);
            #pragma unroll
            for (int mt = 0; mt < 2; mt++) {
                int m = wm + mt * 16 + gid;
                al[mt][0] = Pl[kpo + tig][m];     al[mt][1] = Pl[kpo + tig][m + 8];
                al[mt][2] = Pl[kpo + 4 + tig][m]; al[mt][3] = Pl[kpo + 4 + tig][m + 8];
            }
            #pragma unroll
            for (int mt = 0; mt < 2; mt++)
                #pragma unroll
                for (int nt = 0; nt < 4; nt++)
                    mma16(acc[mt][nt], al[mt], bx[nt]);
            #pragma unroll
            for (int nt = 0; nt < 4; nt++) {
                int n = wn + nt * 8 + gid;
                bx[nt][0] = Vl[kpo + tig][n]; bx[nt][1] = Vl[kpo + 4 + tig][n];
            }
            #pragma unroll
            for (int mt = 0; mt < 2; mt++)
                #pragma unroll
                for (int nt = 0; nt < 4; nt++)
                    mma16(acc[mt][nt], ah[mt], bx[nt]);
        }
        __syncthreads();
    }

    #pragma unroll
    for (int mt = 0; mt < 2; mt++) {
        #pragma unroll
        for (int nt = 0; nt < 4; nt++) {
            int n = wn + nt * 8 + tig * 2;
            #pragma unroll
            for (int h2 = 0; h2 < 2; h2++) {
                int m = qt * 128 + wm + mt * 16 + gid + h2 * 8;
                float2 o = make_float2(acc[mt][nt][h2 * 2], acc[mt][nt][h2 * 2 + 1]);
                *(float2*)&ctx[((size_t)bh_i * NS + m) * NHD + n] = o;
            }
        }
    }
}

// ---------------------------------------------------------------------------
extern "C" void kernel_launch(void* const* d_in, const int* in_sizes, int n_in,
                              void* d_out, int out_size)
{
    (void)in_sizes; (void)n_in;

    const float* query = (const float*)d_in[0];
    const float* key   = (const float*)d_in[1];
    const float* value = (const float*)d_in[2];
    const float* Wq    = (const float*)d_in[3];
    const float* bq    = (const float*)d_in[4];
    const float* Wk    = (const float*)d_in[5];
    const float* bk    = (const float*)d_in[6];
    const float* Wv    = (const float*)d_in[7];
    const float* bv    = (const float*)d_in[8];
    const float* Wo    = (const float*)d_in[9];
    const float* bo    = (const float*)d_in[10];
    const unsigned char* mask = (const unsigned char*)d_in[11];

    float* out = (float*)d_out;

    float *qp, *kp, *vp, *ctxp, *attn;
    cudaGetSymbolAddress((void**)&qp,   g_q);
    cudaGetSymbolAddress((void**)&kp,   g_k);
    cudaGetSymbolAddress((void**)&vp,   g_v);
    cudaGetSymbolAddress((void**)&ctxp, g_ctx);

    if ((long long)out_size >= (long long)OUT_ELEMS + ATTN_ELEMS) {
        attn = out + OUT_ELEMS;             // harness output = concat(out, attn)
    } else {
        cudaGetSymbolAddress((void**)&attn, g_attn_scratch);
    }

    detect_mask_kernel<<<1, 1>>>(mask);

    dim3 blk(256);
    dim3 gproj(ND / 128, NM / 128);  // (8, 32)
    proj_mma_kernel<<<gproj, blk>>>(query, Wq, bq, qp, 0, 1);
    proj_mma_kernel<<<gproj, blk>>>(key,   Wk, bk, kp, 0, 1);
    proj_mma_kernel<<<gproj, blk>>>(value, Wv, bv, vp, 0, 1);

    dim3 gscore(NS / 128, NS / 128, NBH);    // (16, 16, 32)
    score_mma_kernel<<<gscore, blk>>>(qp, kp, mask, attn);

    softmax_kernel<<<NBH * NS, blk>>>(attn);

    dim3 gav(NS / 128, NBH);                 // (16, 32)
    av_mma_kernel<<<gav, blk>>>(attn, vp, ctxp);

    proj_mma_kernel<<<gproj, blk>>>(ctxp, Wo, bo, out, 1, 0);
}